// round 14
// baseline (speedup 1.0000x reference)
#include <cuda_runtime.h>
#include <cuda_fp16.h>
#include <cstdint>
#include <math.h>

#define N_NODES 20000
#define N_EDGES 160000
#define D 512
#define N_GRAPHS 16
#define NODES_PER_GRAPH 1250
#define N_LAYERS 4

// ---------------------------------------------------------------------------
// Device scratch (static globals — no allocations allowed)
// ---------------------------------------------------------------------------
__device__ __half g_hb[N_NODES * D];          // activations fp16 (onorm-scaled, layers 0-2 out)
__device__ __half g_a0[N_NODES * D];          // aggregated GEMM input (fp16)
__device__ __half g_wt[3 * D * D];            // W^T fp16 for layers 0-2, [layer][n][k]
__device__ float g_coef[N_GRAPHS * N_NODES];  // c_g[u] = (1/1250)*sum inorm[v] over edges u->v in g
__device__ float g_pool[N_GRAPHS * D];        // pooled layer-3 agg (fp32)
__device__ float g_onorm[N_NODES];
__device__ float g_inorm[N_NODES];
__device__ int g_outdeg[N_NODES];             // zero at entry (static init / prev fill)
__device__ int g_indeg[N_NODES];
__device__ int g_rowoff[N_NODES + 1];
__device__ int g_cursor[N_NODES];
__device__ int g_csr[N_EDGES];                // src ids grouped by dst

__device__ __forceinline__ uint32_t smem_u32(const void* p) {
    uint32_t a;
    asm("{ .reg .u64 t; cvta.to.shared.u64 t, %1; cvt.u32.u64 %0, t; }" : "=r"(a) : "l"(p));
    return a;
}

__device__ __forceinline__ void cp_async_16(uint32_t dst, const void* src, int src_size) {
    asm volatile("cp.async.cg.shared.global [%0], [%1], 16, %2;"
                 :: "r"(dst), "l"(src), "r"(src_size) : "memory");
}

__device__ __forceinline__ void ldsm_x4(uint32_t* r, uint32_t addr) {
    asm volatile("ldmatrix.sync.aligned.m8n8.x4.shared.b16 {%0,%1,%2,%3}, [%4];"
                 : "=r"(r[0]), "=r"(r[1]), "=r"(r[2]), "=r"(r[3]) : "r"(addr));
}

__device__ __forceinline__ void mma_16816(float* d, const uint32_t* a,
                                          uint32_t b0, uint32_t b1) {
    asm volatile(
        "mma.sync.aligned.m16n8k16.row.col.f32.f16.f16.f32 "
        "{%0,%1,%2,%3}, {%4,%5,%6,%7}, {%8,%9}, {%0,%1,%2,%3};"
        : "+f"(d[0]), "+f"(d[1]), "+f"(d[2]), "+f"(d[3])
        : "r"(a[0]), "r"(a[1]), "r"(a[2]), "r"(a[3]), "r"(b0), "r"(b1));
}

// ---------------------------------------------------------------------------
// Fused: W transpose + fp16 (layers 0-2), degree counting, g_coef zeroing.
// Grid (16,16,3) = 768 blocks x 256 threads = 196608 threads.
// ---------------------------------------------------------------------------
__global__ void wsplit_deg_kernel(const float* __restrict__ W0,
                                  const float* __restrict__ W1,
                                  const float* __restrict__ W2,
                                  const int* __restrict__ src,
                                  const int* __restrict__ dst) {
    __shared__ float tile[32][33];
    int layer = blockIdx.z;
    const float* W = layer == 0 ? W0 : layer == 1 ? W1 : W2;
    int k0 = blockIdx.x * 32, n0 = blockIdx.y * 32;

    int bid = (blockIdx.z * gridDim.y + blockIdx.y) * gridDim.x + blockIdx.x;
    int gtid = bid * 256 + threadIdx.y * 32 + threadIdx.x;
    if (gtid < N_EDGES) {
        atomicAdd(&g_outdeg[src[gtid]], 1);
        atomicAdd(&g_indeg[dst[gtid]], 1);
    }
    // Zero g_coef (320000 entries; 196608 threads -> up to 2 each)
    if (gtid < N_GRAPHS * N_NODES) g_coef[gtid] = 0.0f;
    int gtid2 = gtid + 196608;
    if (gtid2 < N_GRAPHS * N_NODES) g_coef[gtid2] = 0.0f;

    for (int i = threadIdx.y; i < 32; i += 8)
        tile[i][threadIdx.x] = W[(size_t)(k0 + i) * D + n0 + threadIdx.x];
    __syncthreads();
    for (int i = threadIdx.y; i < 32; i += 8) {
        float x = tile[threadIdx.x][i];                       // W[k0+tx][n0+i]
        size_t idx = (size_t)layer * D * D + (size_t)(n0 + i) * D + (k0 + threadIdx.x);
        g_wt[idx] = __float2half(x);
    }
}

// ---------------------------------------------------------------------------
// Fused norms + single-block exclusive scan + g_pool zeroing.
// ---------------------------------------------------------------------------
__global__ void scan_norm_kernel() {
    const int CH = (N_NODES + 1023) / 1024;  // 20
    __shared__ int wsum[32];
    int tid = threadIdx.x;
    int base = tid * CH;

    // Zero g_pool (8192 entries / 1024 threads = 8 each)
#pragma unroll
    for (int i = 0; i < (N_GRAPHS * D) / 1024; i++)
        g_pool[tid + i * 1024] = 0.0f;

    int s = 0;
#pragma unroll 4
    for (int i = 0; i < CH; i++) {
        int idx = base + i;
        if (idx < N_NODES) {
            int id = g_indeg[idx];
            int od = g_outdeg[idx];
            g_inorm[idx] = id > 0 ? rsqrtf((float)id) : 0.0f;
            g_onorm[idx] = od > 0 ? rsqrtf((float)od) : 0.0f;
            s += id;
        }
    }

    int lane = tid & 31, w = tid >> 5;
    int incl = s;
#pragma unroll
    for (int off = 1; off < 32; off <<= 1) {
        int n = __shfl_up_sync(0xffffffffu, incl, off);
        if (lane >= off) incl += n;
    }
    if (lane == 31) wsum[w] = incl;
    __syncthreads();
    if (w == 0) {
        int x = wsum[lane];
#pragma unroll
        for (int off = 1; off < 32; off <<= 1) {
            int n = __shfl_up_sync(0xffffffffu, x, off);
            if (lane >= off) x += n;
        }
        wsum[lane] = x;
    }
    __syncthreads();

    int run = incl - s + (w > 0 ? wsum[w - 1] : 0);
#pragma unroll 4
    for (int i = 0; i < CH; i++) {
        int idx = base + i;
        if (idx < N_NODES) {
            g_rowoff[idx] = run;
            g_cursor[idx] = run;
            run += g_indeg[idx];
        }
    }
    if (tid == 1023) g_rowoff[N_NODES] = wsum[31];
}

// Fill CSR + build layer-3 pooling coefficients; re-zero degree arrays for
// the next invocation (graph replays must be deterministic).
__global__ void fill_kernel(const int* __restrict__ src, const int* __restrict__ dst) {
    int e = blockIdx.x * blockDim.x + threadIdx.x;
    if (e < N_EDGES) {
        int sVal = src[e];
        int d = dst[e];
        int pos = atomicAdd(&g_cursor[d], 1);
        g_csr[pos] = sVal;
        int g = d / NODES_PER_GRAPH;
        atomicAdd(&g_coef[g * N_NODES + sVal],
                  g_inorm[d] * (1.0f / (float)NODES_PER_GRAPH));
    }
    if (e < N_NODES) { g_outdeg[e] = 0; g_indeg[e] = 0; }
}

// ---------------------------------------------------------------------------
// Layer-0 aggregation: fp32 feat, per-edge out_norm weight, fused in_norm, fp16 out.
// ---------------------------------------------------------------------------
__global__ __launch_bounds__(128)
void agg_feat_kernel(const float* __restrict__ h) {
    int node = blockIdx.x;
    int lane4 = threadIdx.x * 4;
    int beg = g_rowoff[node], end = g_rowoff[node + 1];
    float ax = 0.f, ay = 0.f, az = 0.f, aw = 0.f;

    int e = beg;
    for (; e + 4 <= end; e += 4) {
        int s0 = g_csr[e], s1 = g_csr[e + 1], s2 = g_csr[e + 2], s3 = g_csr[e + 3];
        float4 v0 = *reinterpret_cast<const float4*>(&h[(size_t)s0 * D + lane4]);
        float4 v1 = *reinterpret_cast<const float4*>(&h[(size_t)s1 * D + lane4]);
        float4 v2 = *reinterpret_cast<const float4*>(&h[(size_t)s2 * D + lane4]);
        float4 v3 = *reinterpret_cast<const float4*>(&h[(size_t)s3 * D + lane4]);
        float w0 = g_onorm[s0], w1 = g_onorm[s1], w2 = g_onorm[s2], w3 = g_onorm[s3];
        ax = fmaf(v0.x, w0, ax); ay = fmaf(v0.y, w0, ay); az = fmaf(v0.z, w0, az); aw = fmaf(v0.w, w0, aw);
        ax = fmaf(v1.x, w1, ax); ay = fmaf(v1.y, w1, ay); az = fmaf(v1.z, w1, az); aw = fmaf(v1.w, w1, aw);
        ax = fmaf(v2.x, w2, ax); ay = fmaf(v2.y, w2, ay); az = fmaf(v2.z, w2, az); aw = fmaf(v2.w, w2, aw);
        ax = fmaf(v3.x, w3, ax); ay = fmaf(v3.y, w3, ay); az = fmaf(v3.z, w3, az); aw = fmaf(v3.w, w3, aw);
    }
    for (; e < end; ++e) {
        int s = g_csr[e];
        float w = g_onorm[s];
        float4 v = *reinterpret_cast<const float4*>(&h[(size_t)s * D + lane4]);
        ax = fmaf(v.x, w, ax); ay = fmaf(v.y, w, ay);
        az = fmaf(v.z, w, az); aw = fmaf(v.w, w, aw);
    }

    float sc = g_inorm[node];
    __half2 o01 = __floats2half2_rn(ax * sc, ay * sc);
    __half2 o23 = __floats2half2_rn(az * sc, aw * sc);
    uint2 word;
    word.x = *reinterpret_cast<uint32_t*>(&o01);
    word.y = *reinterpret_cast<uint32_t*>(&o23);
    *reinterpret_cast<uint2*>(&g_a0[(size_t)node * D + lane4]) = word;
}

// ---------------------------------------------------------------------------
// Layers 1-2 aggregation: fp16 rows already out_norm-scaled; pure sum.
// ---------------------------------------------------------------------------
__global__ __launch_bounds__(128)
void agg_f16_kernel() {
    int node = blockIdx.x;
    int lane4 = threadIdx.x * 4;
    int beg = g_rowoff[node], end = g_rowoff[node + 1];
    float ax = 0.f, ay = 0.f, az = 0.f, aw = 0.f;

    int e = beg;
    for (; e + 4 <= end; e += 4) {
        int s0 = g_csr[e], s1 = g_csr[e + 1], s2 = g_csr[e + 2], s3 = g_csr[e + 3];
        uint2 u0 = *reinterpret_cast<const uint2*>(&g_hb[(size_t)s0 * D + lane4]);
        uint2 u1 = *reinterpret_cast<const uint2*>(&g_hb[(size_t)s1 * D + lane4]);
        uint2 u2 = *reinterpret_cast<const uint2*>(&g_hb[(size_t)s2 * D + lane4]);
        uint2 u3 = *reinterpret_cast<const uint2*>(&g_hb[(size_t)s3 * D + lane4]);
#pragma unroll
        for (int q = 0; q < 4; q++) {
            uint2 u = q == 0 ? u0 : q == 1 ? u1 : q == 2 ? u2 : u3;
            float2 f01 = __half22float2(*reinterpret_cast<__half2*>(&u.x));
            float2 f23 = __half22float2(*reinterpret_cast<__half2*>(&u.y));
            ax += f01.x; ay += f01.y; az += f23.x; aw += f23.y;
        }
    }
    for (; e < end; ++e) {
        int s = g_csr[e];
        uint2 u = *reinterpret_cast<const uint2*>(&g_hb[(size_t)s * D + lane4]);
        float2 f01 = __half22float2(*reinterpret_cast<__half2*>(&u.x));
        float2 f23 = __half22float2(*reinterpret_cast<__half2*>(&u.y));
        ax += f01.x; ay += f01.y; az += f23.x; aw += f23.y;
    }

    float sc = g_inorm[node];
    __half2 o01 = __floats2half2_rn(ax * sc, ay * sc);
    __half2 o23 = __floats2half2_rn(az * sc, aw * sc);
    uint2 word;
    word.x = *reinterpret_cast<uint32_t*>(&o01);
    word.y = *reinterpret_cast<uint32_t*>(&o23);
    *reinterpret_cast<uint2*>(&g_a0[(size_t)node * D + lane4]) = word;
}

// ---------------------------------------------------------------------------
// fp16 HMMA GEMM (layers 0-2): CTA 128x128, BK=64, 256 threads (8 warps,
// warp tile 32x64), 2-stage cp.async, 72 KB smem -> 2 CTAs/SM.
// Epilogue: g_hb[row] = fp16(out_norm[row] * relu(acc + bias)).
// ---------------------------------------------------------------------------
#define BM 128
#define BN 128
#define BK 64
#define NCHUNK (D / BK)                   // 8
#define PAD_K 72                          // row pitch elements (144 B)
#define TILE_BYTES (128 * PAD_K * 2)      // 18432
#define STAGE_BYTES (2 * TILE_BYTES)      // 36864 (A, B)
#define GEMM_SMEM (2 * STAGE_BYTES)       // 73728

__device__ __forceinline__ void gemm_load_stage(
    uint32_t sb, int c, int m0, int n0, int tid, const __half* wt)
{
    int k0 = c * BK;
    uint32_t stb = sb + (uint32_t)(c & 1) * STAGE_BYTES;
#pragma unroll
    for (int i = 0; i < 8; i++) {
        int id = tid + i * 256;          // 0..2047
        int t = id >> 10;                // 0=A, 1=B
        int r = (id >> 3) & 127;         // row within tile
        int kc = id & 7;                 // 16B chunk within BK
        uint32_t dst = stb + (uint32_t)t * TILE_BYTES + (uint32_t)r * (PAD_K * 2) + kc * 16;
        const __half* g;
        int size = 16;
        if (t == 0) {
            int row = m0 + r;
            if (row >= N_NODES) { row = 0; size = 0; }
            g = g_a0 + (size_t)row * D + k0 + kc * 8;
        } else {
            g = wt + (size_t)(n0 + r) * D + k0 + kc * 8;
        }
        cp_async_16(dst, g, size);
    }
    asm volatile("cp.async.commit_group;" ::: "memory");
}

__global__ __launch_bounds__(256, 2)
void hgemm_kernel(const float* __restrict__ bias, int layer)
{
    extern __shared__ char smem[];
    uint32_t sb = smem_u32(smem);
    int tid = threadIdx.x;
    int lane = tid & 31, wid = tid >> 5;
    int m0 = blockIdx.y * BM;
    int n0 = blockIdx.x * BN;
    int wm = (wid & 3) * 32;
    int wn = (wid >> 2) * 64;

    const __half* wt = g_wt + (size_t)layer * D * D;

    float acc[2][8][4];
#pragma unroll
    for (int i = 0; i < 2; i++)
#pragma unroll
        for (int j = 0; j < 8; j++)
#pragma unroll
            for (int k = 0; k < 4; k++) acc[i][j][k] = 0.0f;

    int lrow = lane & 15;
    uint32_t lcolb = (uint32_t)(lane >> 4) * 16;

    gemm_load_stage(sb, 0, m0, n0, tid, wt);

#pragma unroll 1
    for (int c = 0; c < NCHUNK; ++c) {
        asm volatile("cp.async.wait_group 0;" ::: "memory");
        __syncthreads();
        if (c + 1 < NCHUNK)
            gemm_load_stage(sb, c + 1, m0, n0, tid, wt);   // overlaps compute of c

        uint32_t stb = sb + (uint32_t)(c & 1) * STAGE_BYTES;
        uint32_t at = stb;
        uint32_t bt = stb + TILE_BYTES;

#pragma unroll
        for (int kk = 0; kk < BK; kk += 16) {
            uint32_t kb = (uint32_t)kk * 2 + lcolb;
            uint32_t af[2][4], bf[4][4];
#pragma unroll
            for (int mi = 0; mi < 2; mi++)
                ldsm_x4(af[mi], at + (uint32_t)(wm + mi * 16 + lrow) * (PAD_K * 2) + kb);
#pragma unroll
            for (int nb = 0; nb < 4; nb++)
                ldsm_x4(bf[nb], bt + (uint32_t)(wn + nb * 16 + lrow) * (PAD_K * 2) + kb);
#pragma unroll
            for (int mi = 0; mi < 2; mi++)
#pragma unroll
                for (int nb = 0; nb < 4; nb++) {
                    mma_16816(acc[mi][nb * 2 + 0], af[mi], bf[nb][0], bf[nb][2]);
                    mma_16816(acc[mi][nb * 2 + 1], af[mi], bf[nb][1], bf[nb][3]);
                }
        }
    }

    // Epilogue -> g_hb (fp16): onorm * relu(acc + bias)
    int rbase = m0 + wm + (lane >> 2);
    int cbase = n0 + wn + (lane & 3) * 2;
#pragma unroll
    for (int mi = 0; mi < 2; mi++) {
        int r0 = rbase + mi * 16;
        int r1 = r0 + 8;
        bool v0 = r0 < N_NODES, v1 = r1 < N_NODES;
        float s0 = v0 ? g_onorm[r0] : 0.0f;
        float s1 = v1 ? g_onorm[r1] : 0.0f;
#pragma unroll
        for (int ni = 0; ni < 8; ni++) {
            int col = cbase + ni * 8;
            float2 bv = *reinterpret_cast<const float2*>(&bias[col]);
            float a0 = fmaxf(acc[mi][ni][0] + bv.x, 0.f) * s0;
            float a1 = fmaxf(acc[mi][ni][1] + bv.y, 0.f) * s0;
            float a2 = fmaxf(acc[mi][ni][2] + bv.x, 0.f) * s1;
            float a3 = fmaxf(acc[mi][ni][3] + bv.y, 0.f) * s1;
            __half2 o0 = __floats2half2_rn(a0, a1);
            __half2 o1 = __floats2half2_rn(a2, a3);
            if (v0) *reinterpret_cast<uint32_t*>(&g_hb[(size_t)r0 * D + col]) =
                        *reinterpret_cast<uint32_t*>(&o0);
            if (v1) *reinterpret_cast<uint32_t*>(&g_hb[(size_t)r1 * D + col]) =
                        *reinterpret_cast<uint32_t*>(&o1);
        }
    }
}

// ---------------------------------------------------------------------------
// Layer-3 agg+pool fused via linearity:
//   g_pool[g][c] = sum_u g_coef[g][u] * hb3[u][c]
// Grid 79 blocks x 256 threads; each thread owns 2 columns, acc[16][2] in regs.
// hb3 streamed once (coalesced); coef loads block-uniform (L1 broadcast).
// ---------------------------------------------------------------------------
#define R3_NODES 256
__global__ __launch_bounds__(256)
void reduce3_kernel() {
    int tid = threadIdx.x;
    int ubase = blockIdx.x * R3_NODES;
    int col2 = tid;                                 // half2 column index 0..255

    float accx[N_GRAPHS], accy[N_GRAPHS];
#pragma unroll
    for (int g = 0; g < N_GRAPHS; g++) { accx[g] = 0.f; accy[g] = 0.f; }

    int uend = ubase + R3_NODES;
    if (uend > N_NODES) uend = N_NODES;
    for (int u = ubase; u < uend; ++u) {
        uint32_t w = *reinterpret_cast<const uint32_t*>(
            &g_hb[(size_t)u * D + col2 * 2]);
        float2 f = __half22float2(*reinterpret_cast<__half2*>(&w));
#pragma unroll
        for (int g = 0; g < N_GRAPHS; g++) {
            float cg = g_coef[g * N_NODES + u];     // uniform across block
            accx[g] = fmaf(cg, f.x, accx[g]);
            accy[g] = fmaf(cg, f.y, accy[g]);
        }
    }

#pragma unroll
    for (int g = 0; g < N_GRAPHS; g++) {
        float* p = &g_pool[g * D + col2 * 2];
        asm volatile("red.global.add.v2.f32 [%0], {%1, %2};"
                     :: "l"(p), "f"(accx[g]), "f"(accy[g]) : "memory");
    }
}

// ---------------------------------------------------------------------------
// Mini-GEMM (fp32): out[16,512] = g_pool @ W4 + b4.
// ---------------------------------------------------------------------------
__global__ void minigemm_kernel(const float* __restrict__ W4,
                                const float* __restrict__ b4,
                                float* __restrict__ out) {
    __shared__ float arow[D];
    int g = blockIdx.x;
    int n = blockIdx.y * 128 + threadIdx.x;
    for (int i = threadIdx.x; i < D; i += 128)
        arow[i] = g_pool[g * D + i];
    __syncthreads();
    float s0 = 0.f, s1 = 0.f, s2 = 0.f, s3 = 0.f;
#pragma unroll 4
    for (int k = 0; k < D; k += 4) {
        s0 = fmaf(arow[k + 0], W4[(size_t)(k + 0) * D + n], s0);
        s1 = fmaf(arow[k + 1], W4[(size_t)(k + 1) * D + n], s1);
        s2 = fmaf(arow[k + 2], W4[(size_t)(k + 2) * D + n], s2);
        s3 = fmaf(arow[k + 3], W4[(size_t)(k + 3) * D + n], s3);
    }
    out[g * D + n] = (s0 + s1) + (s2 + s3) + b4[n];
}

// ---------------------------------------------------------------------------
// Launch
// ---------------------------------------------------------------------------
extern "C" void kernel_launch(void* const* d_in, const int* in_sizes, int n_in,
                              void* d_out, int out_size) {
    const float* feat = (const float*)d_in[0];
    const int* src = (const int*)d_in[1];
    const int* dst = (const int*)d_in[2];
    const float* W[4] = {(const float*)d_in[4], (const float*)d_in[6],
                         (const float*)d_in[8], (const float*)d_in[10]};
    const float* B[4] = {(const float*)d_in[5], (const float*)d_in[7],
                         (const float*)d_in[9], (const float*)d_in[11]};
    float* out = (float*)d_out;

    cudaFuncSetAttribute(hgemm_kernel, cudaFuncAttributeMaxDynamicSharedMemorySize,
                         GEMM_SMEM);

    dim3 gemm_grid(D / BN, (N_NODES + BM - 1) / BM);   // (4, 157)

    // Preprocessing: W-convert + degrees + coef-zero; scan+norms+pool-zero;
    // CSR fill + coef build (+deg re-zero for replay determinism)
    wsplit_deg_kernel<<<dim3(D / 32, D / 32, 3), dim3(32, 8)>>>(W[0], W[1], W[2], src, dst);
    scan_norm_kernel<<<1, 1024>>>();
    fill_kernel<<<(N_EDGES + 255) / 256, 256>>>(src, dst);

    // Layers 0-2: agg -> tensor-core GEMM (ReLU + onorm epilogue)
    agg_feat_kernel<<<N_NODES, 128>>>(feat);
    hgemm_kernel<<<gemm_grid, 256, GEMM_SMEM>>>(B[0], 0);
    for (int l = 1; l < 3; l++) {
        agg_f16_kernel<<<N_NODES, 128>>>();
        hgemm_kernel<<<gemm_grid, 256, GEMM_SMEM>>>(B[l], l);
    }

    // Layer 3: fused agg+pool (linearity), then 16x512x512 mini-GEMM.
    reduce3_kernel<<<(N_NODES + R3_NODES - 1) / R3_NODES, 256>>>();
    minigemm_kernel<<<dim3(N_GRAPHS, D / 128), 128>>>(W[3], B[3], out);
}

// round 15
// speedup vs baseline: 1.1513x; 1.1513x over previous
#include <cuda_runtime.h>
#include <cuda_fp16.h>
#include <cstdint>
#include <math.h>

#define N_NODES 20000
#define N_EDGES 160000
#define D 512
#define N_GRAPHS 16
#define NODES_PER_GRAPH 1250

// ---------------------------------------------------------------------------
// Device scratch (static globals — no allocations allowed)
// ---------------------------------------------------------------------------
__device__ __half g_hb[N_NODES * D];          // fp16 feat (pre-GEMM0) then activations
__device__ __half g_a0[N_NODES * D];          // aggregated GEMM input (fp16)
__device__ __half g_wt[3 * D * D];            // W^T fp16 for layers 0-2, [layer][n][k]
__device__ float g_pool[N_GRAPHS * D];        // pooled layer-3 agg (fp32)
__device__ float g_onorm[N_NODES];
__device__ float g_inorm[N_NODES];
__device__ int g_outdeg[N_NODES];             // zero at entry (static init / prev fill)
__device__ int g_indeg[N_NODES];
__device__ int g_rowoff[N_NODES + 1];
__device__ int g_cursor[N_NODES];
__device__ int g_csr[N_EDGES];                // src ids grouped by dst

__device__ __forceinline__ uint32_t smem_u32(const void* p) {
    uint32_t a;
    asm("{ .reg .u64 t; cvta.to.shared.u64 t, %1; cvt.u32.u64 %0, t; }" : "=r"(a) : "l"(p));
    return a;
}

__device__ __forceinline__ void cp_async_16(uint32_t dst, const void* src, int src_size) {
    asm volatile("cp.async.cg.shared.global [%0], [%1], 16, %2;"
                 :: "r"(dst), "l"(src), "r"(src_size) : "memory");
}

__device__ __forceinline__ void ldsm_x4(uint32_t* r, uint32_t addr) {
    asm volatile("ldmatrix.sync.aligned.m8n8.x4.shared.b16 {%0,%1,%2,%3}, [%4];"
                 : "=r"(r[0]), "=r"(r[1]), "=r"(r[2]), "=r"(r[3]) : "r"(addr));
}

__device__ __forceinline__ void mma_16816(float* d, const uint32_t* a,
                                          uint32_t b0, uint32_t b1) {
    asm volatile(
        "mma.sync.aligned.m16n8k16.row.col.f32.f16.f16.f32 "
        "{%0,%1,%2,%3}, {%4,%5,%6,%7}, {%8,%9}, {%0,%1,%2,%3};"
        : "+f"(d[0]), "+f"(d[1]), "+f"(d[2]), "+f"(d[3])
        : "r"(a[0]), "r"(a[1]), "r"(a[2]), "r"(a[3]), "r"(b0), "r"(b1));
}

// ---------------------------------------------------------------------------
// Fused: W transpose + fp16 (layers 0-2), degree counting, feat -> fp16.
// Grid (16,16,3) = 768 blocks x 256 threads = 196608 threads.
// g_hb is dead until hgemm layer 0 writes it -> reuse as fp16 feat buffer.
// ---------------------------------------------------------------------------
__global__ void wsplit_deg_kernel(const float* __restrict__ W0,
                                  const float* __restrict__ W1,
                                  const float* __restrict__ W2,
                                  const int* __restrict__ src,
                                  const int* __restrict__ dst,
                                  const float* __restrict__ feat) {
    __shared__ float tile[32][33];
    int layer = blockIdx.z;
    const float* W = layer == 0 ? W0 : layer == 1 ? W1 : W2;
    int k0 = blockIdx.x * 32, n0 = blockIdx.y * 32;

    int bid = (blockIdx.z * gridDim.y + blockIdx.y) * gridDim.x + blockIdx.x;
    int gtid = bid * 256 + threadIdx.y * 32 + threadIdx.x;
    if (gtid < N_EDGES) {
        atomicAdd(&g_outdeg[src[gtid]], 1);
        atomicAdd(&g_indeg[dst[gtid]], 1);
    }

    // feat -> fp16 into g_hb (grid-strided; 2.56M float4 chunks)
    const int TOT4 = N_NODES * (D / 4);
    const float4* f4 = reinterpret_cast<const float4*>(feat);
    uint2* h4 = reinterpret_cast<uint2*>(g_hb);
    for (int i = gtid; i < TOT4; i += 196608) {
        float4 v = f4[i];
        __half2 a = __floats2half2_rn(v.x, v.y);
        __half2 b = __floats2half2_rn(v.z, v.w);
        uint2 w;
        w.x = *reinterpret_cast<uint32_t*>(&a);
        w.y = *reinterpret_cast<uint32_t*>(&b);
        h4[i] = w;
    }

    for (int i = threadIdx.y; i < 32; i += 8)
        tile[i][threadIdx.x] = W[(size_t)(k0 + i) * D + n0 + threadIdx.x];
    __syncthreads();
    for (int i = threadIdx.y; i < 32; i += 8) {
        float x = tile[threadIdx.x][i];                       // W[k0+tx][n0+i]
        size_t idx = (size_t)layer * D * D + (size_t)(n0 + i) * D + (k0 + threadIdx.x);
        g_wt[idx] = __float2half(x);
    }
}

// ---------------------------------------------------------------------------
// Fused norms + single-block exclusive scan + g_pool zeroing.
// ---------------------------------------------------------------------------
__global__ void scan_norm_kernel() {
    const int CH = (N_NODES + 1023) / 1024;  // 20
    __shared__ int wsum[32];
    int tid = threadIdx.x;
    int base = tid * CH;

    // Zero g_pool (8192 entries / 1024 threads = 8 each) — replay-deterministic
#pragma unroll
    for (int i = 0; i < (N_GRAPHS * D) / 1024; i++)
        g_pool[tid + i * 1024] = 0.0f;

    int s = 0;
#pragma unroll 4
    for (int i = 0; i < CH; i++) {
        int idx = base + i;
        if (idx < N_NODES) {
            int id = g_indeg[idx];
            int od = g_outdeg[idx];
            g_inorm[idx] = id > 0 ? rsqrtf((float)id) : 0.0f;
            g_onorm[idx] = od > 0 ? rsqrtf((float)od) : 0.0f;
            s += id;
        }
    }

    int lane = tid & 31, w = tid >> 5;
    int incl = s;
#pragma unroll
    for (int off = 1; off < 32; off <<= 1) {
        int n = __shfl_up_sync(0xffffffffu, incl, off);
        if (lane >= off) incl += n;
    }
    if (lane == 31) wsum[w] = incl;
    __syncthreads();
    if (w == 0) {
        int x = wsum[lane];
#pragma unroll
        for (int off = 1; off < 32; off <<= 1) {
            int n = __shfl_up_sync(0xffffffffu, x, off);
            if (lane >= off) x += n;
        }
        wsum[lane] = x;
    }
    __syncthreads();

    int run = incl - s + (w > 0 ? wsum[w - 1] : 0);
#pragma unroll 4
    for (int i = 0; i < CH; i++) {
        int idx = base + i;
        if (idx < N_NODES) {
            g_rowoff[idx] = run;
            g_cursor[idx] = run;
            run += g_indeg[idx];
        }
    }
    if (tid == 1023) g_rowoff[N_NODES] = wsum[31];
}

// Fill CSR; re-zero degree arrays for the next invocation (replay determinism).
__global__ void fill_kernel(const int* __restrict__ src, const int* __restrict__ dst) {
    int e = blockIdx.x * blockDim.x + threadIdx.x;
    if (e < N_EDGES) {
        int d = dst[e];
        int pos = atomicAdd(&g_cursor[d], 1);
        g_csr[pos] = src[e];
    }
    if (e < N_NODES) { g_outdeg[e] = 0; g_indeg[e] = 0; }
}

// ---------------------------------------------------------------------------
// Layer-0 aggregation: fp16 feat (in g_hb), per-edge out_norm weight,
// fused in_norm, fp16 out to g_a0.
// ---------------------------------------------------------------------------
__global__ __launch_bounds__(128)
void agg0_kernel() {
    int node = blockIdx.x;
    int lane4 = threadIdx.x * 4;
    int beg = g_rowoff[node], end = g_rowoff[node + 1];
    float ax = 0.f, ay = 0.f, az = 0.f, aw = 0.f;

    int e = beg;
    for (; e + 4 <= end; e += 4) {
        int s0 = g_csr[e], s1 = g_csr[e + 1], s2 = g_csr[e + 2], s3 = g_csr[e + 3];
        uint2 u0 = *reinterpret_cast<const uint2*>(&g_hb[(size_t)s0 * D + lane4]);
        uint2 u1 = *reinterpret_cast<const uint2*>(&g_hb[(size_t)s1 * D + lane4]);
        uint2 u2 = *reinterpret_cast<const uint2*>(&g_hb[(size_t)s2 * D + lane4]);
        uint2 u3 = *reinterpret_cast<const uint2*>(&g_hb[(size_t)s3 * D + lane4]);
        float w0 = g_onorm[s0], w1 = g_onorm[s1], w2 = g_onorm[s2], w3 = g_onorm[s3];
#pragma unroll
        for (int q = 0; q < 4; q++) {
            uint2 u = q == 0 ? u0 : q == 1 ? u1 : q == 2 ? u2 : u3;
            float w = q == 0 ? w0 : q == 1 ? w1 : q == 2 ? w2 : w3;
            float2 f01 = __half22float2(*reinterpret_cast<__half2*>(&u.x));
            float2 f23 = __half22float2(*reinterpret_cast<__half2*>(&u.y));
            ax = fmaf(f01.x, w, ax); ay = fmaf(f01.y, w, ay);
            az = fmaf(f23.x, w, az); aw = fmaf(f23.y, w, aw);
        }
    }
    for (; e < end; ++e) {
        int s = g_csr[e];
        float w = g_onorm[s];
        uint2 u = *reinterpret_cast<const uint2*>(&g_hb[(size_t)s * D + lane4]);
        float2 f01 = __half22float2(*reinterpret_cast<__half2*>(&u.x));
        float2 f23 = __half22float2(*reinterpret_cast<__half2*>(&u.y));
        ax = fmaf(f01.x, w, ax); ay = fmaf(f01.y, w, ay);
        az = fmaf(f23.x, w, az); aw = fmaf(f23.y, w, aw);
    }

    float sc = g_inorm[node];
    __half2 o01 = __floats2half2_rn(ax * sc, ay * sc);
    __half2 o23 = __floats2half2_rn(az * sc, aw * sc);
    uint2 word;
    word.x = *reinterpret_cast<uint32_t*>(&o01);
    word.y = *reinterpret_cast<uint32_t*>(&o23);
    *reinterpret_cast<uint2*>(&g_a0[(size_t)node * D + lane4]) = word;
}

// ---------------------------------------------------------------------------
// Layers 1-2 aggregation: fp16 rows already out_norm-scaled; pure sum -> g_a0.
// ---------------------------------------------------------------------------
__global__ __launch_bounds__(128)
void agg_f16_kernel() {
    int node = blockIdx.x;
    int lane4 = threadIdx.x * 4;
    int beg = g_rowoff[node], end = g_rowoff[node + 1];
    float ax = 0.f, ay = 0.f, az = 0.f, aw = 0.f;

    int e = beg;
    for (; e + 4 <= end; e += 4) {
        int s0 = g_csr[e], s1 = g_csr[e + 1], s2 = g_csr[e + 2], s3 = g_csr[e + 3];
        uint2 u0 = *reinterpret_cast<const uint2*>(&g_hb[(size_t)s0 * D + lane4]);
        uint2 u1 = *reinterpret_cast<const uint2*>(&g_hb[(size_t)s1 * D + lane4]);
        uint2 u2 = *reinterpret_cast<const uint2*>(&g_hb[(size_t)s2 * D + lane4]);
        uint2 u3 = *reinterpret_cast<const uint2*>(&g_hb[(size_t)s3 * D + lane4]);
#pragma unroll
        for (int q = 0; q < 4; q++) {
            uint2 u = q == 0 ? u0 : q == 1 ? u1 : q == 2 ? u2 : u3;
            float2 f01 = __half22float2(*reinterpret_cast<__half2*>(&u.x));
            float2 f23 = __half22float2(*reinterpret_cast<__half2*>(&u.y));
            ax += f01.x; ay += f01.y; az += f23.x; aw += f23.y;
        }
    }
    for (; e < end; ++e) {
        int s = g_csr[e];
        uint2 u = *reinterpret_cast<const uint2*>(&g_hb[(size_t)s * D + lane4]);
        float2 f01 = __half22float2(*reinterpret_cast<__half2*>(&u.x));
        float2 f23 = __half22float2(*reinterpret_cast<__half2*>(&u.y));
        ax += f01.x; ay += f01.y; az += f23.x; aw += f23.y;
    }

    float sc = g_inorm[node];
    __half2 o01 = __floats2half2_rn(ax * sc, ay * sc);
    __half2 o23 = __floats2half2_rn(az * sc, aw * sc);
    uint2 word;
    word.x = *reinterpret_cast<uint32_t*>(&o01);
    word.y = *reinterpret_cast<uint32_t*>(&o23);
    *reinterpret_cast<uint2*>(&g_a0[(size_t)node * D + lane4]) = word;
}

// ---------------------------------------------------------------------------
// Layer-3 aggregation fused with mean-pool: the agg output's only consumer
// is the (linear) pool, so each node adds inorm*sum/1250 straight into
// g_pool[graph] via red.global (no g_a0 roundtrip, no pool kernel).
// ---------------------------------------------------------------------------
__global__ __launch_bounds__(128)
void agg3_pool_kernel() {
    int node = blockIdx.x;
    int lane4 = threadIdx.x * 4;
    int beg = g_rowoff[node], end = g_rowoff[node + 1];
    float ax = 0.f, ay = 0.f, az = 0.f, aw = 0.f;

    int e = beg;
    for (; e + 4 <= end; e += 4) {
        int s0 = g_csr[e], s1 = g_csr[e + 1], s2 = g_csr[e + 2], s3 = g_csr[e + 3];
        uint2 u0 = *reinterpret_cast<const uint2*>(&g_hb[(size_t)s0 * D + lane4]);
        uint2 u1 = *reinterpret_cast<const uint2*>(&g_hb[(size_t)s1 * D + lane4]);
        uint2 u2 = *reinterpret_cast<const uint2*>(&g_hb[(size_t)s2 * D + lane4]);
        uint2 u3 = *reinterpret_cast<const uint2*>(&g_hb[(size_t)s3 * D + lane4]);
#pragma unroll
        for (int q = 0; q < 4; q++) {
            uint2 u = q == 0 ? u0 : q == 1 ? u1 : q == 2 ? u2 : u3;
            float2 f01 = __half22float2(*reinterpret_cast<__half2*>(&u.x));
            float2 f23 = __half22float2(*reinterpret_cast<__half2*>(&u.y));
            ax += f01.x; ay += f01.y; az += f23.x; aw += f23.y;
        }
    }
    for (; e < end; ++e) {
        int s = g_csr[e];
        uint2 u = *reinterpret_cast<const uint2*>(&g_hb[(size_t)s * D + lane4]);
        float2 f01 = __half22float2(*reinterpret_cast<__half2*>(&u.x));
        float2 f23 = __half22float2(*reinterpret_cast<__half2*>(&u.y));
        ax += f01.x; ay += f01.y; az += f23.x; aw += f23.y;
    }

    float sc = g_inorm[node] * (1.0f / (float)NODES_PER_GRAPH);
    int g = node / NODES_PER_GRAPH;
    float* p = &g_pool[g * D + lane4];
    asm volatile("red.global.add.v4.f32 [%0], {%1, %2, %3, %4};"
                 :: "l"(p), "f"(ax * sc), "f"(ay * sc), "f"(az * sc), "f"(aw * sc)
                 : "memory");
}

// ---------------------------------------------------------------------------
// fp16 HMMA GEMM (layers 0-2): CTA 128x128, BK=64, 256 threads (8 warps,
// warp tile 32x64), 2-stage cp.async, 72 KB smem -> 2 CTAs/SM.
// Epilogue: g_hb[row] = fp16(out_norm[row] * relu(acc + bias)).
// ---------------------------------------------------------------------------
#define BM 128
#define BN 128
#define BK 64
#define NCHUNK (D / BK)                   // 8
#define PAD_K 72                          // row pitch elements (144 B)
#define TILE_BYTES (128 * PAD_K * 2)      // 18432
#define STAGE_BYTES (2 * TILE_BYTES)      // 36864 (A, B)
#define GEMM_SMEM (2 * STAGE_BYTES)       // 73728

__device__ __forceinline__ void gemm_load_stage(
    uint32_t sb, int c, int m0, int n0, int tid, const __half* wt)
{
    int k0 = c * BK;
    uint32_t stb = sb + (uint32_t)(c & 1) * STAGE_BYTES;
#pragma unroll
    for (int i = 0; i < 8; i++) {
        int id = tid + i * 256;          // 0..2047
        int t = id >> 10;                // 0=A, 1=B
        int r = (id >> 3) & 127;         // row within tile
        int kc = id & 7;                 // 16B chunk within BK
        uint32_t dst = stb + (uint32_t)t * TILE_BYTES + (uint32_t)r * (PAD_K * 2) + kc * 16;
        const __half* g;
        int size = 16;
        if (t == 0) {
            int row = m0 + r;
            if (row >= N_NODES) { row = 0; size = 0; }
            g = g_a0 + (size_t)row * D + k0 + kc * 8;
        } else {
            g = wt + (size_t)(n0 + r) * D + k0 + kc * 8;
        }
        cp_async_16(dst, g, size);
    }
    asm volatile("cp.async.commit_group;" ::: "memory");
}

__global__ __launch_bounds__(256, 2)
void hgemm_kernel(const float* __restrict__ bias, int layer)
{
    extern __shared__ char smem[];
    uint32_t sb = smem_u32(smem);
    int tid = threadIdx.x;
    int lane = tid & 31, wid = tid >> 5;
    int m0 = blockIdx.y * BM;
    int n0 = blockIdx.x * BN;
    int wm = (wid & 3) * 32;
    int wn = (wid >> 2) * 64;

    const __half* wt = g_wt + (size_t)layer * D * D;

    float acc[2][8][4];
#pragma unroll
    for (int i = 0; i < 2; i++)
#pragma unroll
        for (int j = 0; j < 8; j++)
#pragma unroll
            for (int k = 0; k < 4; k++) acc[i][j][k] = 0.0f;

    int lrow = lane & 15;
    uint32_t lcolb = (uint32_t)(lane >> 4) * 16;

    gemm_load_stage(sb, 0, m0, n0, tid, wt);

#pragma unroll 1
    for (int c = 0; c < NCHUNK; ++c) {
        asm volatile("cp.async.wait_group 0;" ::: "memory");
        __syncthreads();
        if (c + 1 < NCHUNK)
            gemm_load_stage(sb, c + 1, m0, n0, tid, wt);   // overlaps compute of c

        uint32_t stb = sb + (uint32_t)(c & 1) * STAGE_BYTES;
        uint32_t at = stb;
        uint32_t bt = stb + TILE_BYTES;

#pragma unroll
        for (int kk = 0; kk < BK; kk += 16) {
            uint32_t kb = (uint32_t)kk * 2 + lcolb;
            uint32_t af[2][4], bf[4][4];
#pragma unroll
            for (int mi = 0; mi < 2; mi++)
                ldsm_x4(af[mi], at + (uint32_t)(wm + mi * 16 + lrow) * (PAD_K * 2) + kb);
#pragma unroll
            for (int nb = 0; nb < 4; nb++)
                ldsm_x4(bf[nb], bt + (uint32_t)(wn + nb * 16 + lrow) * (PAD_K * 2) + kb);
#pragma unroll
            for (int mi = 0; mi < 2; mi++)
#pragma unroll
                for (int nb = 0; nb < 4; nb++) {
                    mma_16816(acc[mi][nb * 2 + 0], af[mi], bf[nb][0], bf[nb][2]);
                    mma_16816(acc[mi][nb * 2 + 1], af[mi], bf[nb][1], bf[nb][3]);
                }
        }
    }

    // Epilogue -> g_hb (fp16): onorm * relu(acc + bias)
    int rbase = m0 + wm + (lane >> 2);
    int cbase = n0 + wn + (lane & 3) * 2;
#pragma unroll
    for (int mi = 0; mi < 2; mi++) {
        int r0 = rbase + mi * 16;
        int r1 = r0 + 8;
        bool v0 = r0 < N_NODES, v1 = r1 < N_NODES;
        float s0 = v0 ? g_onorm[r0] : 0.0f;
        float s1 = v1 ? g_onorm[r1] : 0.0f;
#pragma unroll
        for (int ni = 0; ni < 8; ni++) {
            int col = cbase + ni * 8;
            float2 bv = *reinterpret_cast<const float2*>(&bias[col]);
            float a0 = fmaxf(acc[mi][ni][0] + bv.x, 0.f) * s0;
            float a1 = fmaxf(acc[mi][ni][1] + bv.y, 0.f) * s0;
            float a2 = fmaxf(acc[mi][ni][2] + bv.x, 0.f) * s1;
            float a3 = fmaxf(acc[mi][ni][3] + bv.y, 0.f) * s1;
            __half2 o0 = __floats2half2_rn(a0, a1);
            __half2 o1 = __floats2half2_rn(a2, a3);
            if (v0) *reinterpret_cast<uint32_t*>(&g_hb[(size_t)r0 * D + col]) =
                        *reinterpret_cast<uint32_t*>(&o0);
            if (v1) *reinterpret_cast<uint32_t*>(&g_hb[(size_t)r1 * D + col]) =
                        *reinterpret_cast<uint32_t*>(&o1);
        }
    }
}

// ---------------------------------------------------------------------------
// Mini-GEMM (fp32): out[16,512] = g_pool @ W4 + b4.
// ---------------------------------------------------------------------------
__global__ void minigemm_kernel(const float* __restrict__ W4,
                                const float* __restrict__ b4,
                                float* __restrict__ out) {
    __shared__ float arow[D];
    int g = blockIdx.x;
    int n = blockIdx.y * 128 + threadIdx.x;
    for (int i = threadIdx.x; i < D; i += 128)
        arow[i] = g_pool[g * D + i];
    __syncthreads();
    float s0 = 0.f, s1 = 0.f, s2 = 0.f, s3 = 0.f;
#pragma unroll 4
    for (int k = 0; k < D; k += 4) {
        s0 = fmaf(arow[k + 0], W4[(size_t)(k + 0) * D + n], s0);
        s1 = fmaf(arow[k + 1], W4[(size_t)(k + 1) * D + n], s1);
        s2 = fmaf(arow[k + 2], W4[(size_t)(k + 2) * D + n], s2);
        s3 = fmaf(arow[k + 3], W4[(size_t)(k + 3) * D + n], s3);
    }
    out[g * D + n] = (s0 + s1) + (s2 + s3) + b4[n];
}

// ---------------------------------------------------------------------------
// Launch (11 kernels)
// ---------------------------------------------------------------------------
extern "C" void kernel_launch(void* const* d_in, const int* in_sizes, int n_in,
                              void* d_out, int out_size) {
    const float* feat = (const float*)d_in[0];
    const int* src = (const int*)d_in[1];
    const int* dst = (const int*)d_in[2];
    const float* W[4] = {(const float*)d_in[4], (const float*)d_in[6],
                         (const float*)d_in[8], (const float*)d_in[10]};
    const float* B[4] = {(const float*)d_in[5], (const float*)d_in[7],
                         (const float*)d_in[9], (const float*)d_in[11]};
    float* out = (float*)d_out;

    cudaFuncSetAttribute(hgemm_kernel, cudaFuncAttributeMaxDynamicSharedMemorySize,
                         GEMM_SMEM);

    dim3 gemm_grid(D / BN, (N_NODES + BM - 1) / BM);   // (4, 157)

    // Preprocessing: W-convert + degrees + feat->fp16; scan+norms+pool-zero;
    // CSR fill (+deg re-zero for replay determinism)
    wsplit_deg_kernel<<<dim3(D / 32, D / 32, 3), dim3(32, 8)>>>(W[0], W[1], W[2],
                                                                src, dst, feat);
    scan_norm_kernel<<<1, 1024>>>();
    fill_kernel<<<(N_EDGES + 255) / 256, 256>>>(src, dst);

    // Layers 0-2: agg -> tensor-core GEMM (ReLU + onorm epilogue)
    agg0_kernel<<<N_NODES, 128>>>();
    hgemm_kernel<<<gemm_grid, 256, GEMM_SMEM>>>(B[0], 0);
    for (int l = 1; l < 3; l++) {
        agg_f16_kernel<<<N_NODES, 128>>>();
        hgemm_kernel<<<gemm_grid, 256, GEMM_SMEM>>>(B[l], l);
    }

    // Layer 3: agg fused with mean-pool (red.global into g_pool), then mini-GEMM.
    agg3_pool_kernel<<<N_NODES, 128>>>();
    minigemm_kernel<<<dim3(N_GRAPHS, D / 128), 128>>>(W[3], B[3], out);
}